// round 10
// baseline (speedup 1.0000x reference)
#include <cuda_runtime.h>
#include <cuda_bf16.h>
#include <math.h>
#include <stdint.h>

#define Bsz   4
#define Tq    196
#define Lseq  392
#define DM    1024
#define DI    2048
#define DS    16
#define DTR   64
#define MROWS (Bsz*Lseq)   /* 1568 */
#define M2    (Bsz*Tq)     /* 784  */

typedef __nv_bfloat16 bf16;

// ---------------- scratch (static device globals; no allocation) -------------
__device__ float g_embt [Bsz*DM];
__device__ float g_seq  [MROWS*DM];
__device__ float g_dbc  [MROWS*96];
__device__ float g_delta[(size_t)MROWS*DI];
__device__ float g_part [(size_t)8*MROWS*96 > (size_t)2*M2*DM ? (size_t)8*MROWS*96 : (size_t)2*M2*DM];

// bf16 buffers
__device__ bf16 g_xnormh[(size_t)MROWS*DM];
__device__ bf16 g_xzh   [(size_t)MROWS*2*DI];
__device__ bf16 g_xch   [(size_t)MROWS*DI];
__device__ bf16 g_dbch  [MROWS*96];
__device__ bf16 g_yzh   [(size_t)M2*DI];
__device__ bf16 g_wih   [(size_t)4096*DM];
__device__ bf16 g_wxh   [96*DI];
__device__ bf16 g_wdh   [DI*DTR];
__device__ bf16 g_woh   [(size_t)DM*DI];

// ---------------- helpers -----------------------------------------------------
__device__ __forceinline__ void mma16(float c[4], const uint32_t a[4], const uint32_t b[2]) {
    asm volatile(
        "mma.sync.aligned.m16n8k16.row.col.f32.bf16.bf16.f32 "
        "{%0,%1,%2,%3},{%4,%5,%6,%7},{%8,%9},{%0,%1,%2,%3};\n"
        : "+f"(c[0]), "+f"(c[1]), "+f"(c[2]), "+f"(c[3])
        : "r"(a[0]), "r"(a[1]), "r"(a[2]), "r"(a[3]), "r"(b[0]), "r"(b[1]));
}

__device__ __forceinline__ void ldsm4(uint32_t &r0, uint32_t &r1, uint32_t &r2, uint32_t &r3,
                                      uint32_t addr) {
    asm volatile("ldmatrix.sync.aligned.m8n8.x4.shared.b16 {%0,%1,%2,%3}, [%4];"
        : "=r"(r0), "=r"(r1), "=r"(r2), "=r"(r3) : "r"(addr));
}

#define CP16(dst, src) asm volatile("cp.async.cg.shared.global [%0], [%1], 16;\n" :: "r"(dst), "l"(src))
#define CP_COMMIT()    asm volatile("cp.async.commit_group;\n")
#define CP_WAIT1()     asm volatile("cp.async.wait_group 1;\n")
#define CP_WAIT0()     asm volatile("cp.async.wait_group 0;\n")

__device__ __forceinline__ void store2(float* C, size_t off, float v0, float v1) {
    *(float2*)&C[off] = make_float2(v0, v1);
}
__device__ __forceinline__ void store2(bf16* C, size_t off, float v0, float v1) {
    *(__nv_bfloat162*)&C[off] = __floats2bfloat162_rn(v0, v1);
}

// ---------------- cvt fp32 -> bf16 (x4 vectorized) ----------------------------
__global__ void k_cvt4(const float* __restrict__ src, bf16* __restrict__ dst, int n4) {
    int i = blockIdx.x * 256 + threadIdx.x;
    if (i >= n4) return;
    float4 v = *(const float4*)&src[i*4];
    __nv_bfloat162 lo = __floats2bfloat162_rn(v.x, v.y);
    __nv_bfloat162 hi = __floats2bfloat162_rn(v.z, v.w);
    *(uint2*)&dst[i*4] = make_uint2(*(uint32_t*)&lo, *(uint32_t*)&hi);
}

// ---------------- K_time: temb + 2-layer MLP fused (one block per batch) -----
__global__ void __launch_bounds__(1024) k_time(const int* __restrict__ ts,
        const float* __restrict__ w1, const float* __restrict__ b1,
        const float* __restrict__ w2, const float* __restrict__ b2) {
    __shared__ float temb_s[1024];
    __shared__ float h_s[2048];
    int b = blockIdx.x, t = threadIdx.x;
    float tt = (float)ts[b];
    if (t < 512) {
        float freq = __expf(-logf(10000.f) * (float)t / 512.f);
        temb_s[t]       = cosf(tt * freq);
        temb_s[t + 512] = sinf(tt * freq);
    }
    __syncthreads();
    int warp = t >> 5, lane = t & 31;
    // phase1: h = silu(temb @ w1^T + b1), N=2048, K=1024
    for (int o = warp; o < 2048; o += 32) {
        const float* w = w1 + (size_t)o * 1024;
        float s = 0.f;
        for (int k = lane*4; k < 1024; k += 128) {
            float4 wv = *(const float4*)&w[k];
            float4 xv = *(const float4*)&temb_s[k];
            s += wv.x*xv.x + wv.y*xv.y + wv.z*xv.z + wv.w*xv.w;
        }
        #pragma unroll
        for (int o2 = 16; o2; o2 >>= 1) s += __shfl_xor_sync(~0u, s, o2);
        if (lane == 0) {
            float v = s + b1[o];
            h_s[o] = v / (1.f + expf(-v));
        }
    }
    __syncthreads();
    // phase2: embt = h @ w2^T + b2, N=1024, K=2048
    for (int o = warp; o < 1024; o += 32) {
        const float* w = w2 + (size_t)o * 2048;
        float s = 0.f;
        for (int k = lane*4; k < 2048; k += 128) {
            float4 wv = *(const float4*)&w[k];
            float4 xv = *(const float4*)&h_s[k];
            s += wv.x*xv.x + wv.y*xv.y + wv.z*xv.z + wv.w*xv.w;
        }
        #pragma unroll
        for (int o2 = 16; o2; o2 >>= 1) s += __shfl_xor_sync(~0u, s, o2);
        if (lane == 0) g_embt[b*DM + o] = s + b2[o];
    }
}

// ---------------- K_embed: embed + LN -> seq(fp32), RMS -> xnorm(bf16) -------
__global__ void k_embed(const float* __restrict__ x_r, const float* __restrict__ motion,
                        const float* __restrict__ pos,
                        const float* __restrict__ ln_g, const float* __restrict__ ln_b,
                        const float* __restrict__ rms_w) {
    int l = blockIdx.x;
    int b = blockIdx.y;
    int t = threadIdx.x;
    __shared__ float r1[8], r2[8];

    float loc[4];
    float s1 = 0.f, s2 = 0.f;
    #pragma unroll
    for (int i = 0; i < 4; i++) {
        int d = t + i*256;
        float v;
        if (l < Tq) {
            v = pos[l*DM + d] + motion[(size_t)(b*Tq + l)*DM + d];
        } else {
            int lr = l - Tq;
            v = pos[lr*DM + d] + x_r[(size_t)(b*Tq + lr)*DM + d] + g_embt[b*DM + d];
        }
        loc[i] = v; s1 += v; s2 += v*v;
    }
    int lane = t & 31, w = t >> 5;
    #pragma unroll
    for (int o = 16; o; o >>= 1) { s1 += __shfl_xor_sync(~0u, s1, o); s2 += __shfl_xor_sync(~0u, s2, o); }
    if (lane == 0) { r1[w] = s1; r2[w] = s2; }
    __syncthreads();
    if (t == 0) {
        float a = 0.f, c = 0.f;
        #pragma unroll
        for (int i = 0; i < 8; i++) { a += r1[i]; c += r2[i]; }
        r1[0] = a; r2[0] = c;
    }
    __syncthreads();
    float mu = r1[0] * (1.f/DM);
    float var = r2[0] * (1.f/DM) - mu*mu;
    float rstd = rsqrtf(var + 1e-5f);
    __syncthreads();

    float q = 0.f;
    size_t row = (size_t)(b*Lseq + l)*DM;
    #pragma unroll
    for (int i = 0; i < 4; i++) {
        int d = t + i*256;
        float ln = (loc[i] - mu) * rstd * ln_g[d] + ln_b[d];
        loc[i] = ln;
        q += ln*ln;
        g_seq[row + d] = ln;
    }
    #pragma unroll
    for (int o = 16; o; o >>= 1) q += __shfl_xor_sync(~0u, q, o);
    if (lane == 0) r1[w] = q;
    __syncthreads();
    if (t == 0) {
        float a = 0.f;
        #pragma unroll
        for (int i = 0; i < 8; i++) a += r1[i];
        r1[0] = a;
    }
    __syncthreads();
    float rrms = rsqrtf(r1[0] * (1.f/DM) + 1e-5f);
    #pragma unroll
    for (int i = 0; i < 4; i++) {
        int d = t + i*256;
        g_xnormh[row + d] = __float2bfloat16_rn(loc[i] * rrms * rms_w[d]);
    }
}

// ---------------- HGEMM: C[M,N] = A[M,K].B[N,K]^T, bf16 mma, 3-stage ---------
// 128x128 block, 256 threads (8 warps: 2m x 4n, warp tile 64x32), BK=16.
// ldmatrix fragment loads, 1 sync/iter. EPI==1: softplus(v+bias) (CT=float).
template<int EPI, typename CT>
__global__ void __launch_bounds__(256)
hgemm(const bf16* __restrict__ A, const bf16* __restrict__ B,
      CT* __restrict__ C, int M, int N, int lda, int ldb,
      int klen, const float* __restrict__ bias) {
    __shared__ bf16 As[3][128][24];
    __shared__ bf16 Bs[3][128][24];
    int tid = threadIdx.x;
    int bm0 = blockIdx.y * 128;
    int bn0 = blockIdx.x * 128;
    int kbeg = blockIdx.z * klen;
    C += (size_t)blockIdx.z * M * N;

    int warp = tid >> 5, lane = tid & 31;
    int wm = (warp & 1) * 64;
    int wn = (warp >> 1) * 32;
    int g = lane >> 2, r = lane & 3;

    float c[4][4][4];
    #pragma unroll
    for (int i = 0; i < 4; i++)
        #pragma unroll
        for (int j = 0; j < 4; j++)
            #pragma unroll
            for (int q = 0; q < 4; q++) c[i][j][q] = 0.f;

    int row_ld = tid >> 1;            // 0..127
    int ch_ld  = (tid & 1) * 8;       // halves

    const int STAGE_B = 128*24*2;     // 6144 bytes per stage
    uint32_t sA = (uint32_t)__cvta_generic_to_shared(&As[0][0][0]);
    uint32_t sB = (uint32_t)__cvta_generic_to_shared(&Bs[0][0][0]);
    // ldmatrix lane addresses
    uint32_t aoff = (uint32_t)(((wm + (lane & 7) + ((lane >> 3) & 1) * 8) * 24) * 2
                               + ((lane >> 4) & 1) * 16);
    uint32_t boff = (uint32_t)(((wn + ((lane >> 4) & 1) * 8 + (lane & 7)) * 24) * 2
                               + ((lane >> 3) & 1) * 16);

    auto prefetch = [&](int kt) {
        int s = kt % 3;
        int k0 = kbeg + kt * 16 + ch_ld;
        int gm = min(bm0 + row_ld, M - 1);
        CP16((uint32_t)__cvta_generic_to_shared(&As[s][row_ld][ch_ld]),
             &A[(size_t)gm * lda + k0]);
        int gn = min(bn0 + row_ld, N - 1);
        CP16((uint32_t)__cvta_generic_to_shared(&Bs[s][row_ld][ch_ld]),
             &B[(size_t)gn * ldb + k0]);
    };

    int nk = klen / 16;
    prefetch(0); CP_COMMIT();
    if (nk > 1) { prefetch(1); CP_COMMIT(); }

    for (int kt = 0; kt < nk; kt++) {
        if (kt == nk - 1) { CP_WAIT0(); } else { CP_WAIT1(); }
        __syncthreads();
        int s = kt % 3;
        uint32_t bA = sA + s*STAGE_B;
        uint32_t bB = sB + s*STAGE_B;

        uint32_t bfr[4][2];
        ldsm4(bfr[0][0], bfr[0][1], bfr[1][0], bfr[1][1], bB + boff);
        ldsm4(bfr[2][0], bfr[2][1], bfr[3][0], bfr[3][1], bB + boff + 16*48);
        #pragma unroll
        for (int i = 0; i < 4; i++) {
            uint32_t a[4];
            ldsm4(a[0], a[1], a[2], a[3], bA + aoff + i*16*48);
            #pragma unroll
            for (int j = 0; j < 4; j++)
                mma16(c[i][j], a, bfr[j]);
        }
        if (kt + 2 < nk) { prefetch(kt + 2); CP_COMMIT(); }
    }

    // epilogue
    #pragma unroll
    for (int i = 0; i < 4; i++) {
        #pragma unroll
        for (int half = 0; half < 2; half++) {
            int m = bm0 + wm + i*16 + g + half*8;
            if (m >= M) continue;
            #pragma unroll
            for (int j = 0; j < 4; j++) {
                int n = bn0 + wn + j*8 + 2*r;
                if (n >= N) continue;
                float v0 = c[i][j][half*2 + 0];
                float v1 = c[i][j][half*2 + 1];
                if (EPI == 1) {
                    v0 += bias[n];
                    v0 = (v0 > 20.f) ? v0 : log1pf(expf(v0));
                    v1 += bias[n + 1];
                    v1 = (v1 > 20.f) ? v1 : log1pf(expf(v1));
                }
                store2(C, (size_t)m*N + n, v0, v1);
            }
        }
    }
}

// ---------------- split-K reduce (x_proj) + bf16 copy ------------------------
__global__ void k_reduce(const float* __restrict__ part, float* __restrict__ out,
                         bf16* __restrict__ outh, int MN, int S) {
    int i = blockIdx.x * 256 + threadIdx.x;
    if (i >= MN) return;
    float s = 0.f;
    for (int z = 0; z < S; z++) s += part[(size_t)z*MN + i];
    out[i] = s;
    outh[i] = __float2bfloat16_rn(s);
}

// ---------------- K_conv: depthwise causal conv (w=4) + silu (bf16 io) -------
__global__ void k_conv(const float* __restrict__ cw, const float* __restrict__ cb) {
    int idx = blockIdx.x*256 + threadIdx.x;
    if (idx >= MROWS*DI) return;
    int e = idx & (DI-1);
    int bl = idx >> 11;
    int l = bl % Lseq;
    const bf16* base = g_xzh + (size_t)bl*(2*DI) + e;
    float s = cb[e];
    s = fmaf(__bfloat162float(base[0]), cw[e*4+3], s);
    if (l >= 1) s = fmaf(__bfloat162float(base[-(2*DI)]),   cw[e*4+2], s);
    if (l >= 2) s = fmaf(__bfloat162float(base[-2*(2*DI)]), cw[e*4+1], s);
    if (l >= 3) s = fmaf(__bfloat162float(base[-3*(2*DI)]), cw[e*4+0], s);
    g_xch[idx] = __float2bfloat16_rn(s / (1.f + expf(-s)));
}

// ---------------- K_scan: selective scan + fused gating (sw pipelined) -------
__global__ void k_scan(const float* __restrict__ A_log, const float* __restrict__ Dp) {
    int gtid = blockIdx.x*blockDim.x + threadIdx.x;
    int grp = gtid >> 4;
    int n = gtid & 15;
    int b = grp >> 11;
    int e = grp & (DI-1);
    float Ac = -expf(A_log[e*DS + n]);
    float Dv = Dp[e];
    float h = 0.f;
    const float* dptr = g_delta + (size_t)b*Lseq*DI + e;
    const bf16*  uptr = g_xch   + (size_t)b*Lseq*DI + e;
    const float* bc   = g_dbc   + (size_t)b*Lseq*96;
    const bf16*  zptr = g_xzh   + (size_t)b*Lseq*4096 + DI + e;
    bf16* yzp         = g_yzh   + (size_t)b*Tq*DI + e;

    // prefetch first iteration
    float dv = dptr[0];
    float u  = __bfloat162float(uptr[0]);
    float Bv = bc[64 + n];
    float Cv = bc[80 + n];

    for (int l = 0; l < Lseq; l++) {
        float dv_n = 0.f, u_n = 0.f, Bv_n = 0.f, Cv_n = 0.f;
        if (l + 1 < Lseq) {
            dv_n = dptr[(size_t)(l+1)*DI];
            u_n  = __bfloat162float(uptr[(size_t)(l+1)*DI]);
            Bv_n = bc[(l+1)*96 + 64 + n];
            Cv_n = bc[(l+1)*96 + 80 + n];
        }
        h = fmaf(__expf(dv*Ac), h, dv*Bv*u);
        if (l >= Tq) {
            float p = h*Cv;
            p += __shfl_xor_sync(0xffffffffu, p, 1);
            p += __shfl_xor_sync(0xffffffffu, p, 2);
            p += __shfl_xor_sync(0xffffffffu, p, 4);
            p += __shfl_xor_sync(0xffffffffu, p, 8);
            if (n == 0) {
                float z = __bfloat162float(zptr[(size_t)l*4096]);
                float gate = z / (1.f + expf(-z));
                yzp[(size_t)(l - Tq)*DI] = __float2bfloat16_rn((p + u*Dv) * gate);
            }
        }
        dv = dv_n; u = u_n; Bv = Bv_n; Cv = Cv_n;
    }
}

// ---------------- K_final: residual + split-K reduce + layernorm -------------
__global__ void k_final(const float* __restrict__ ln_g, const float* __restrict__ ln_b,
                        float* __restrict__ out) {
    int lr = blockIdx.x;
    int b  = blockIdx.y;
    int t  = threadIdx.x;
    __shared__ float r1[8], r2[8];
    size_t srow = (size_t)(b*Lseq + Tq + lr)*DM;
    size_t mrow = (size_t)(b*Tq + lr)*DM;

    float loc[4];
    float s1 = 0.f, s2 = 0.f;
    #pragma unroll
    for (int i = 0; i < 4; i++) {
        int d = t + i*256;
        float v = g_seq[srow + d] + g_part[mrow + d] + g_part[(size_t)M2*DM + mrow + d];
        loc[i] = v; s1 += v; s2 += v*v;
    }
    int lane = t & 31, w = t >> 5;
    #pragma unroll
    for (int o = 16; o; o >>= 1) { s1 += __shfl_xor_sync(~0u, s1, o); s2 += __shfl_xor_sync(~0u, s2, o); }
    if (lane == 0) { r1[w] = s1; r2[w] = s2; }
    __syncthreads();
    if (t == 0) {
        float a = 0.f, c = 0.f;
        #pragma unroll
        for (int i = 0; i < 8; i++) { a += r1[i]; c += r2[i]; }
        r1[0] = a; r2[0] = c;
    }
    __syncthreads();
    float mu = r1[0] * (1.f/DM);
    float var = r2[0] * (1.f/DM) - mu*mu;
    float rstd = rsqrtf(var + 1e-5f);
    #pragma unroll
    for (int i = 0; i < 4; i++) {
        int d = t + i*256;
        out[mrow + d] = (loc[i] - mu) * rstd * ln_g[d] + ln_b[d];
    }
}

// ---------------- launch ------------------------------------------------------
extern "C" void kernel_launch(void* const* d_in, const int* in_sizes, int n_in,
                              void* d_out, int out_size) {
    const float* x_r       = (const float*)d_in[0];
    const int*   timesteps = (const int*)  d_in[1];
    const float* motion    = (const float*)d_in[2];
    const float* time_w1   = (const float*)d_in[3];
    const float* time_b1   = (const float*)d_in[4];
    const float* time_w2   = (const float*)d_in[5];
    const float* time_b2   = (const float*)d_in[6];
    const float* pos_emb   = (const float*)d_in[7];
    const float* ln_g      = (const float*)d_in[8];
    const float* ln_b      = (const float*)d_in[9];
    const float* in_proj_w = (const float*)d_in[10];
    const float* conv_w    = (const float*)d_in[11];
    const float* conv_b    = (const float*)d_in[12];
    const float* x_proj_w  = (const float*)d_in[13];
    const float* dt_proj_w = (const float*)d_in[14];
    const float* dt_proj_b = (const float*)d_in[15];
    const float* A_log     = (const float*)d_in[16];
    const float* Dp        = (const float*)d_in[17];
    const float* out_proj_w= (const float*)d_in[18];
    const float* rms_w     = (const float*)d_in[19];
    float* out = (float*)d_out;

    float *p_dbc, *p_delta, *p_part;
    bf16 *p_xnormh, *p_xzh, *p_xch, *p_dbch, *p_yzh, *p_wih, *p_wxh, *p_wdh, *p_woh;
    cudaGetSymbolAddress((void**)&p_dbc,   g_dbc);
    cudaGetSymbolAddress((void**)&p_delta, g_delta);
    cudaGetSymbolAddress((void**)&p_part,  g_part);
    cudaGetSymbolAddress((void**)&p_xnormh,g_xnormh);
    cudaGetSymbolAddress((void**)&p_xzh,   g_xzh);
    cudaGetSymbolAddress((void**)&p_xch,   g_xch);
    cudaGetSymbolAddress((void**)&p_dbch,  g_dbch);
    cudaGetSymbolAddress((void**)&p_yzh,   g_yzh);
    cudaGetSymbolAddress((void**)&p_wih,   g_wih);
    cudaGetSymbolAddress((void**)&p_wxh,   g_wxh);
    cudaGetSymbolAddress((void**)&p_wdh,   g_wdh);
    cudaGetSymbolAddress((void**)&p_woh,   g_woh);

    // 1: in_proj weight cvt
    k_cvt4<<<(4096*DM/4 + 255)/256, 256>>>(in_proj_w,  p_wih, 4096*DM/4);
    // 2: fused time embedding + MLP
    k_time<<<Bsz, 1024>>>(timesteps, time_w1, time_b1, time_w2, time_b2);
    // 3: embed + LN -> seq, rms -> xnorm (bf16)
    k_embed<<<dim3(Lseq, Bsz), 256>>>(x_r, motion, pos_emb, ln_g, ln_b, rms_w);
    // 4: in_proj (PROFILED SLOT): xz(bf16) = xnorm @ in_proj_w^T  [1568x4096] K=1024
    hgemm<0, bf16><<<dim3(4096/128, (MROWS+127)/128, 1), 256>>>(
        p_xnormh, p_wih, p_xzh, MROWS, 4096, DM, DM, DM, nullptr);
    // 5-7: remaining weight cvts
    k_cvt4<<<(96*DI/4  + 255)/256, 256>>>(x_proj_w,   p_wxh, 96*DI/4);
    k_cvt4<<<(DI*DTR/4 + 255)/256, 256>>>(dt_proj_w,  p_wdh, DI*DTR/4);
    k_cvt4<<<(DM*DI/4  + 255)/256, 256>>>(out_proj_w, p_woh, DM*DI/4);
    // 8: depthwise conv + silu (bf16)
    k_conv<<<(MROWS*DI + 255)/256, 256>>>(conv_w, conv_b);
    // 9: x_proj: dbc = xc @ x_proj_w^T  [1568x96] K=2048 split-8
    hgemm<0, float><<<dim3(1, (MROWS+127)/128, 8), 256>>>(
        p_xch, p_wxh, p_part, MROWS, 96, DI, DI, DI/8, nullptr);
    // 10: reduce partials (fp32 + bf16)
    k_reduce<<<(MROWS*96 + 255)/256, 256>>>(p_part, p_dbc, p_dbch, MROWS*96, 8);
    // 11: dt_proj + softplus  [1568x2048] K=64
    hgemm<1, float><<<dim3(DI/128, (MROWS+127)/128, 1), 256>>>(
        p_dbch, p_wdh, p_delta, MROWS, DI, 96, DTR, DTR, dt_proj_b);
    // 12: selective scan + fused gating -> yz (bf16)
    k_scan<<<(Bsz*DI*DS)/256, 256>>>(A_log, Dp);
    // 13: out_proj partials  [784x1024] K=2048 split-2
    hgemm<0, float><<<dim3(DM/128, (M2+127)/128, 2), 256>>>(
        p_yzh, p_woh, p_part, M2, DM, DI, DI, DI/2, nullptr);
    // 14: residual + split-K reduce + final LN
    k_final<<<dim3(Tq, Bsz), 256>>>(ln_g, ln_b, out);
}

// round 13
// speedup vs baseline: 1.5707x; 1.5707x over previous
#include <cuda_runtime.h>
#include <cuda_bf16.h>
#include <math.h>
#include <stdint.h>

#define Bsz   4
#define Tq    196
#define Lseq  392
#define DM    1024
#define DI    2048
#define DS    16
#define DTR   64
#define MROWS (Bsz*Lseq)   /* 1568 */
#define M2    (Bsz*Tq)     /* 784  */

typedef __nv_bfloat16 bf16;

// ---------------- scratch (static device globals; no allocation) -------------
__device__ float g_temb [Bsz*DM];
__device__ float g_hmlp [Bsz*2048];
__device__ float g_embt [Bsz*DM];
__device__ float g_seq  [MROWS*DM];
__device__ float g_dbc  [MROWS*96];
__device__ float g_delta[(size_t)MROWS*DI];
__device__ float g_part [(size_t)8*MROWS*96 > (size_t)2*M2*DM ? (size_t)8*MROWS*96 : (size_t)2*M2*DM];

// bf16 buffers
__device__ bf16 g_xnormh[(size_t)MROWS*DM];
__device__ bf16 g_xzh   [(size_t)MROWS*2*DI];
__device__ bf16 g_xch   [(size_t)MROWS*DI];
__device__ bf16 g_dbch  [MROWS*96];
__device__ bf16 g_yzh   [(size_t)M2*DI];
__device__ bf16 g_wih   [(size_t)4096*DM];
__device__ bf16 g_wxh   [96*DI];
__device__ bf16 g_wdh   [DI*DTR];
__device__ bf16 g_woh   [(size_t)DM*DI];

// ---------------- helpers -----------------------------------------------------
__device__ __forceinline__ void mma16(float c[4], const uint32_t a[4], const uint32_t b[2]) {
    asm volatile(
        "mma.sync.aligned.m16n8k16.row.col.f32.bf16.bf16.f32 "
        "{%0,%1,%2,%3},{%4,%5,%6,%7},{%8,%9},{%0,%1,%2,%3};\n"
        : "+f"(c[0]), "+f"(c[1]), "+f"(c[2]), "+f"(c[3])
        : "r"(a[0]), "r"(a[1]), "r"(a[2]), "r"(a[3]), "r"(b[0]), "r"(b[1]));
}

__device__ __forceinline__ void ldsm4(uint32_t &r0, uint32_t &r1, uint32_t &r2, uint32_t &r3,
                                      uint32_t addr) {
    asm volatile("ldmatrix.sync.aligned.m8n8.x4.shared.b16 {%0,%1,%2,%3}, [%4];"
        : "=r"(r0), "=r"(r1), "=r"(r2), "=r"(r3) : "r"(addr));
}

#define CP16(dst, src) asm volatile("cp.async.cg.shared.global [%0], [%1], 16;\n" :: "r"(dst), "l"(src))
#define CP_COMMIT()    asm volatile("cp.async.commit_group;\n")
#define CP_WAIT1()     asm volatile("cp.async.wait_group 1;\n")
#define CP_WAIT0()     asm volatile("cp.async.wait_group 0;\n")

__device__ __forceinline__ void store2(float* C, size_t off, float v0, float v1) {
    *(float2*)&C[off] = make_float2(v0, v1);
}
__device__ __forceinline__ void store2(bf16* C, size_t off, float v0, float v1) {
    *(__nv_bfloat162*)&C[off] = __floats2bfloat162_rn(v0, v1);
}

// ---------------- cvt fp32 -> bf16 (x4 vectorized) ----------------------------
__global__ void k_cvt4(const float* __restrict__ src, bf16* __restrict__ dst, int n4) {
    int i = blockIdx.x * 256 + threadIdx.x;
    if (i >= n4) return;
    float4 v = *(const float4*)&src[i*4];
    __nv_bfloat162 lo = __floats2bfloat162_rn(v.x, v.y);
    __nv_bfloat162 hi = __floats2bfloat162_rn(v.z, v.w);
    *(uint2*)&dst[i*4] = make_uint2(*(uint32_t*)&lo, *(uint32_t*)&hi);
}

// ---------------- K1: timestep embedding -------------------------------------
__global__ void k_temb(const int* __restrict__ ts) {
    int b = blockIdx.x;
    int i = threadIdx.x;                 // 512 threads
    float t = (float)ts[b];
    float freq = expf(-logf(10000.0f) * (float)i / 512.0f);
    float arg = t * freq;
    g_temb[b*DM + i]       = cosf(arg);
    g_temb[b*DM + 512 + i] = sinf(arg);
}

// ---------------- K2/K3: tiny MLP via warp-per-output GEMV -------------------
__global__ void k_mlp(const float* __restrict__ X, const float* __restrict__ W,
                      const float* __restrict__ bias, float* __restrict__ Y,
                      int K, int N, int act) {
    int warp = (blockIdx.x * blockDim.x + threadIdx.x) >> 5;
    int lane = threadIdx.x & 31;
    int b = blockIdx.y;
    if (warp >= N) return;
    const float* x = X + b*K;
    const float* w = W + (size_t)warp*K;
    float s = 0.f;
    for (int k = lane; k < K; k += 32) s = fmaf(x[k], w[k], s);
    #pragma unroll
    for (int o = 16; o; o >>= 1) s += __shfl_xor_sync(0xffffffffu, s, o);
    if (lane == 0) {
        float v = s + bias[warp];
        if (act) v = v / (1.f + expf(-v));
        Y[b*N + warp] = v;
    }
}

// ---------------- K_embed: embed + LN -> seq(fp32), RMS -> xnorm(bf16) -------
__global__ void k_embed(const float* __restrict__ x_r, const float* __restrict__ motion,
                        const float* __restrict__ pos,
                        const float* __restrict__ ln_g, const float* __restrict__ ln_b,
                        const float* __restrict__ rms_w) {
    int l = blockIdx.x;
    int b = blockIdx.y;
    int t = threadIdx.x;
    __shared__ float r1[8], r2[8];

    float loc[4];
    float s1 = 0.f, s2 = 0.f;
    #pragma unroll
    for (int i = 0; i < 4; i++) {
        int d = t + i*256;
        float v;
        if (l < Tq) {
            v = pos[l*DM + d] + motion[(size_t)(b*Tq + l)*DM + d];
        } else {
            int lr = l - Tq;
            v = pos[lr*DM + d] + x_r[(size_t)(b*Tq + lr)*DM + d] + g_embt[b*DM + d];
        }
        loc[i] = v; s1 += v; s2 += v*v;
    }
    int lane = t & 31, w = t >> 5;
    #pragma unroll
    for (int o = 16; o; o >>= 1) { s1 += __shfl_xor_sync(~0u, s1, o); s2 += __shfl_xor_sync(~0u, s2, o); }
    if (lane == 0) { r1[w] = s1; r2[w] = s2; }
    __syncthreads();
    if (t == 0) {
        float a = 0.f, c = 0.f;
        #pragma unroll
        for (int i = 0; i < 8; i++) { a += r1[i]; c += r2[i]; }
        r1[0] = a; r2[0] = c;
    }
    __syncthreads();
    float mu = r1[0] * (1.f/DM);
    float var = r2[0] * (1.f/DM) - mu*mu;
    float rstd = rsqrtf(var + 1e-5f);
    __syncthreads();

    float q = 0.f;
    size_t row = (size_t)(b*Lseq + l)*DM;
    #pragma unroll
    for (int i = 0; i < 4; i++) {
        int d = t + i*256;
        float ln = (loc[i] - mu) * rstd * ln_g[d] + ln_b[d];
        loc[i] = ln;
        q += ln*ln;
        g_seq[row + d] = ln;
    }
    #pragma unroll
    for (int o = 16; o; o >>= 1) q += __shfl_xor_sync(~0u, q, o);
    if (lane == 0) r1[w] = q;
    __syncthreads();
    if (t == 0) {
        float a = 0.f;
        #pragma unroll
        for (int i = 0; i < 8; i++) a += r1[i];
        r1[0] = a;
    }
    __syncthreads();
    float rrms = rsqrtf(r1[0] * (1.f/DM) + 1e-5f);
    #pragma unroll
    for (int i = 0; i < 4; i++) {
        int d = t + i*256;
        g_xnormh[row + d] = __float2bfloat16_rn(loc[i] * rrms * rms_w[d]);
    }
}

// ---------------- HGEMM: C[M,N] = A[M,K].B[N,K]^T, bf16 mma, 3-stage, BK=32 --
// 128x128 block, 256 threads (8 warps: 2m x 4n, warp tile 64x32).
// smem row stride 40 halves (80B): ldmatrix banks all-distinct.
// EPI==1: softplus(v+bias) (CT=float).
#define SSTR 40                     /* halves per smem row */
template<int EPI, typename CT>
__global__ void __launch_bounds__(256)
hgemm(const bf16* __restrict__ A, const bf16* __restrict__ B,
      CT* __restrict__ C, int M, int N, int lda, int ldb,
      int klen, const float* __restrict__ bias) {
    __shared__ bf16 As[3][128][SSTR];
    __shared__ bf16 Bs[3][128][SSTR];
    int tid = threadIdx.x;
    int bm0 = blockIdx.y * 128;
    int bn0 = blockIdx.x * 128;
    int kbeg = blockIdx.z * klen;
    C += (size_t)blockIdx.z * M * N;

    int warp = tid >> 5, lane = tid & 31;
    int wm = (warp & 1) * 64;
    int wn = (warp >> 1) * 32;
    int g = lane >> 2, r = lane & 3;

    float c[4][4][4];
    #pragma unroll
    for (int i = 0; i < 4; i++)
        #pragma unroll
        for (int j = 0; j < 4; j++)
            #pragma unroll
            for (int q = 0; q < 4; q++) c[i][j][q] = 0.f;

    int row_ld = tid >> 2;            // 0..63
    int ch_ld  = (tid & 3) * 8;       // halves: 0,8,16,24

    const int STAGE_B = 128*SSTR*2;   // 10240 bytes per stage
    uint32_t sA = (uint32_t)__cvta_generic_to_shared(&As[0][0][0]);
    uint32_t sB = (uint32_t)__cvta_generic_to_shared(&Bs[0][0][0]);
    // ldmatrix lane base addresses (within k-half 0)
    uint32_t aoff = (uint32_t)((wm + (lane & 7) + ((lane >> 3) & 1) * 8) * (SSTR*2)
                               + ((lane >> 4) & 1) * 16);
    uint32_t boff = (uint32_t)((wn + ((lane >> 4) & 1) * 8 + (lane & 7)) * (SSTR*2)
                               + ((lane >> 3) & 1) * 16);

    auto prefetch = [&](int kt) {
        int s = kt % 3;
        int k0 = kbeg + kt * 32 + ch_ld;
        #pragma unroll
        for (int u = 0; u < 2; u++) {
            int row = row_ld + u*64;
            int gm = min(bm0 + row, M - 1);
            CP16((uint32_t)__cvta_generic_to_shared(&As[s][row][ch_ld]),
                 &A[(size_t)gm * lda + k0]);
            int gn = min(bn0 + row, N - 1);
            CP16((uint32_t)__cvta_generic_to_shared(&Bs[s][row][ch_ld]),
                 &B[(size_t)gn * ldb + k0]);
        }
    };

    int nk = klen / 32;
    prefetch(0); CP_COMMIT();
    if (nk > 1) { prefetch(1); CP_COMMIT(); }

    for (int kt = 0; kt < nk; kt++) {
        if (kt == nk - 1) { CP_WAIT0(); } else { CP_WAIT1(); }
        __syncthreads();
        int s = kt % 3;
        uint32_t bA = sA + s*STAGE_B;
        uint32_t bB = sB + s*STAGE_B;

        #pragma unroll
        for (int kh = 0; kh < 2; kh++) {
            uint32_t ko = kh * 32;     // byte offset for second 16-K half
            uint32_t bfr[4][2];
            ldsm4(bfr[0][0], bfr[0][1], bfr[1][0], bfr[1][1], bB + boff + ko);
            ldsm4(bfr[2][0], bfr[2][1], bfr[3][0], bfr[3][1], bB + boff + 16*(SSTR*2) + ko);
            #pragma unroll
            for (int i = 0; i < 4; i++) {
                uint32_t a[4];
                ldsm4(a[0], a[1], a[2], a[3], bA + aoff + i*16*(SSTR*2) + ko);
                #pragma unroll
                for (int j = 0; j < 4; j++)
                    mma16(c[i][j], a, bfr[j]);
            }
        }
        if (kt + 2 < nk) { prefetch(kt + 2); CP_COMMIT(); }
    }

    // epilogue
    #pragma unroll
    for (int i = 0; i < 4; i++) {
        #pragma unroll
        for (int half = 0; half < 2; half++) {
            int m = bm0 + wm + i*16 + g + half*8;
            if (m >= M) continue;
            #pragma unroll
            for (int j = 0; j < 4; j++) {
                int n = bn0 + wn + j*8 + 2*r;
                if (n >= N) continue;
                float v0 = c[i][j][half*2 + 0];
                float v1 = c[i][j][half*2 + 1];
                if (EPI == 1) {
                    v0 += bias[n];
                    v0 = (v0 > 20.f) ? v0 : log1pf(expf(v0));
                    v1 += bias[n + 1];
                    v1 = (v1 > 20.f) ? v1 : log1pf(expf(v1));
                }
                store2(C, (size_t)m*N + n, v0, v1);
            }
        }
    }
}

// ---------------- split-K reduce (x_proj) + bf16 copy ------------------------
__global__ void k_reduce(const float* __restrict__ part, float* __restrict__ out,
                         bf16* __restrict__ outh, int MN, int S) {
    int i = blockIdx.x * 256 + threadIdx.x;
    if (i >= MN) return;
    float s = 0.f;
    for (int z = 0; z < S; z++) s += part[(size_t)z*MN + i];
    out[i] = s;
    outh[i] = __float2bfloat16_rn(s);
}

// ---------------- K_conv: depthwise causal conv (w=4) + silu (bf16 io) -------
__global__ void k_conv(const float* __restrict__ cw, const float* __restrict__ cb) {
    int idx = blockIdx.x*256 + threadIdx.x;
    if (idx >= MROWS*DI) return;
    int e = idx & (DI-1);
    int bl = idx >> 11;
    int l = bl % Lseq;
    const bf16* base = g_xzh + (size_t)bl*(2*DI) + e;
    float s = cb[e];
    s = fmaf(__bfloat162float(base[0]), cw[e*4+3], s);
    if (l >= 1) s = fmaf(__bfloat162float(base[-(2*DI)]),   cw[e*4+2], s);
    if (l >= 2) s = fmaf(__bfloat162float(base[-2*(2*DI)]), cw[e*4+1], s);
    if (l >= 3) s = fmaf(__bfloat162float(base[-3*(2*DI)]), cw[e*4+0], s);
    g_xch[idx] = __float2bfloat16_rn(s / (1.f + expf(-s)));
}

// ---------------- K_scan: selective scan + fused gating (sw pipelined) -------
__global__ void k_scan(const float* __restrict__ A_log, const float* __restrict__ Dp) {
    int gtid = blockIdx.x*blockDim.x + threadIdx.x;
    int grp = gtid >> 4;
    int n = gtid & 15;
    int b = grp >> 11;
    int e = grp & (DI-1);
    float Ac = -expf(A_log[e*DS + n]);
    float Dv = Dp[e];
    float h = 0.f;
    const float* dptr = g_delta + (size_t)b*Lseq*DI + e;
    const bf16*  uptr = g_xch   + (size_t)b*Lseq*DI + e;
    const float* bc   = g_dbc   + (size_t)b*Lseq*96;
    const bf16*  zptr = g_xzh   + (size_t)b*Lseq*4096 + DI + e;
    bf16* yzp         = g_yzh   + (size_t)b*Tq*DI + e;

    float dv = dptr[0];
    float u  = __bfloat162float(uptr[0]);
    float Bv = bc[64 + n];
    float Cv = bc[80 + n];

    for (int l = 0; l < Lseq; l++) {
        float dv_n = 0.f, u_n = 0.f, Bv_n = 0.f, Cv_n = 0.f;
        if (l + 1 < Lseq) {
            dv_n = dptr[(size_t)(l+1)*DI];
            u_n  = __bfloat162float(uptr[(size_t)(l+1)*DI]);
            Bv_n = bc[(l+1)*96 + 64 + n];
            Cv_n = bc[(l+1)*96 + 80 + n];
        }
        h = fmaf(__expf(dv*Ac), h, dv*Bv*u);
        if (l >= Tq) {
            float p = h*Cv;
            p += __shfl_xor_sync(0xffffffffu, p, 1);
            p += __shfl_xor_sync(0xffffffffu, p, 2);
            p += __shfl_xor_sync(0xffffffffu, p, 4);
            p += __shfl_xor_sync(0xffffffffu, p, 8);
            if (n == 0) {
                float z = __bfloat162float(zptr[(size_t)l*4096]);
                float gate = z / (1.f + expf(-z));
                yzp[(size_t)(l - Tq)*DI] = __float2bfloat16_rn((p + u*Dv) * gate);
            }
        }
        dv = dv_n; u = u_n; Bv = Bv_n; Cv = Cv_n;
    }
}

// ---------------- K_final: residual + split-K reduce + layernorm -------------
__global__ void k_final(const float* __restrict__ ln_g, const float* __restrict__ ln_b,
                        float* __restrict__ out) {
    int lr = blockIdx.x;
    int b  = blockIdx.y;
    int t  = threadIdx.x;
    __shared__ float r1[8], r2[8];
    size_t srow = (size_t)(b*Lseq + Tq + lr)*DM;
    size_t mrow = (size_t)(b*Tq + lr)*DM;

    float loc[4];
    float s1 = 0.f, s2 = 0.f;
    #pragma unroll
    for (int i = 0; i < 4; i++) {
        int d = t + i*256;
        float v = g_seq[srow + d] + g_part[mrow + d] + g_part[(size_t)M2*DM + mrow + d];
        loc[i] = v; s1 += v; s2 += v*v;
    }
    int lane = t & 31, w = t >> 5;
    #pragma unroll
    for (int o = 16; o; o >>= 1) { s1 += __shfl_xor_sync(~0u, s1, o); s2 += __shfl_xor_sync(~0u, s2, o); }
    if (lane == 0) { r1[w] = s1; r2[w] = s2; }
    __syncthreads();
    if (t == 0) {
        float a = 0.f, c = 0.f;
        #pragma unroll
        for (int i = 0; i < 8; i++) { a += r1[i]; c += r2[i]; }
        r1[0] = a; r2[0] = c;
    }
    __syncthreads();
    float mu = r1[0] * (1.f/DM);
    float var = r2[0] * (1.f/DM) - mu*mu;
    float rstd = rsqrtf(var + 1e-5f);
    #pragma unroll
    for (int i = 0; i < 4; i++) {
        int d = t + i*256;
        out[mrow + d] = (loc[i] - mu) * rstd * ln_g[d] + ln_b[d];
    }
}

// ---------------- launch ------------------------------------------------------
extern "C" void kernel_launch(void* const* d_in, const int* in_sizes, int n_in,
                              void* d_out, int out_size) {
    const float* x_r       = (const float*)d_in[0];
    const int*   timesteps = (const int*)  d_in[1];
    const float* motion    = (const float*)d_in[2];
    const float* time_w1   = (const float*)d_in[3];
    const float* time_b1   = (const float*)d_in[4];
    const float* time_w2   = (const float*)d_in[5];
    const float* time_b2   = (const float*)d_in[6];
    const float* pos_emb   = (const float*)d_in[7];
    const float* ln_g      = (const float*)d_in[8];
    const float* ln_b      = (const float*)d_in[9];
    const float* in_proj_w = (const float*)d_in[10];
    const float* conv_w    = (const float*)d_in[11];
    const float* conv_b    = (const float*)d_in[12];
    const float* x_proj_w  = (const float*)d_in[13];
    const float* dt_proj_w = (const float*)d_in[14];
    const float* dt_proj_b = (const float*)d_in[15];
    const float* A_log     = (const float*)d_in[16];
    const float* Dp        = (const float*)d_in[17];
    const float* out_proj_w= (const float*)d_in[18];
    const float* rms_w     = (const float*)d_in[19];
    float* out = (float*)d_out;

    float *p_temb, *p_h, *p_embt, *p_dbc, *p_delta, *p_part;
    bf16 *p_xnormh, *p_xzh, *p_xch, *p_dbch, *p_yzh, *p_wih, *p_wxh, *p_wdh, *p_woh;
    cudaGetSymbolAddress((void**)&p_temb,  g_temb);
    cudaGetSymbolAddress((void**)&p_h,     g_hmlp);
    cudaGetSymbolAddress((void**)&p_embt,  g_embt);
    cudaGetSymbolAddress((void**)&p_dbc,   g_dbc);
    cudaGetSymbolAddress((void**)&p_delta, g_delta);
    cudaGetSymbolAddress((void**)&p_part,  g_part);
    cudaGetSymbolAddress((void**)&p_xnormh,g_xnormh);
    cudaGetSymbolAddress((void**)&p_xzh,   g_xzh);
    cudaGetSymbolAddress((void**)&p_xch,   g_xch);
    cudaGetSymbolAddress((void**)&p_dbch,  g_dbch);
    cudaGetSymbolAddress((void**)&p_yzh,   g_yzh);
    cudaGetSymbolAddress((void**)&p_wih,   g_wih);
    cudaGetSymbolAddress((void**)&p_wxh,   g_wxh);
    cudaGetSymbolAddress((void**)&p_wdh,   g_wdh);
    cudaGetSymbolAddress((void**)&p_woh,   g_woh);

    // in_proj weight cvt
    k_cvt4<<<(4096*DM/4 + 255)/256, 256>>>(in_proj_w,  p_wih, 4096*DM/4);
    // time embedding + MLP (wide grids — NOT the fused 4-CTA version)
    k_temb<<<Bsz, 512>>>(timesteps);
    k_mlp<<<dim3(2048/8, Bsz), 256>>>(p_temb, time_w1, time_b1, p_h, 1024, 2048, 1);
    k_mlp<<<dim3(1024/8, Bsz), 256>>>(p_h, time_w2, time_b2, p_embt, 2048, 1024, 0);
    // embed + LN -> seq, rms -> xnorm (bf16)
    k_embed<<<dim3(Lseq, Bsz), 256>>>(x_r, motion, pos_emb, ln_g, ln_b, rms_w);
    // in_proj: xz(bf16) = xnorm @ in_proj_w^T  [1568x4096] K=1024
    hgemm<0, bf16><<<dim3(4096/128, (MROWS+127)/128, 1), 256>>>(
        p_xnormh, p_wih, p_xzh, MROWS, 4096, DM, DM, DM, nullptr);
    // remaining weight cvts
    k_cvt4<<<(96*DI/4  + 255)/256, 256>>>(x_proj_w,   p_wxh, 96*DI/4);
    k_cvt4<<<(DI*DTR/4 + 255)/256, 256>>>(dt_proj_w,  p_wdh, DI*DTR/4);
    k_cvt4<<<(DM*DI/4  + 255)/256, 256>>>(out_proj_w, p_woh, DM*DI/4);
    // depthwise conv + silu (bf16)
    k_conv<<<(MROWS*DI + 255)/256, 256>>>(conv_w, conv_b);
    // x_proj: dbc = xc @ x_proj_w^T  [1568x96] K=2048 split-8
    hgemm<0, float><<<dim3(1, (MROWS+127)/128, 8), 256>>>(
        p_xch, p_wxh, p_part, MROWS, 96, DI, DI, DI/8, nullptr);
    // reduce partials (fp32 + bf16)
    k_reduce<<<(MROWS*96 + 255)/256, 256>>>(p_part, p_dbc, p_dbch, MROWS*96, 8);
    // dt_proj + softplus  [1568x2048] K=64
    hgemm<1, float><<<dim3(DI/128, (MROWS+127)/128, 1), 256>>>(
        p_dbch, p_wdh, p_delta, MROWS, DI, 96, DTR, DTR, dt_proj_b);
    // selective scan + fused gating -> yz (bf16)
    k_scan<<<(Bsz*DI*DS)/256, 256>>>(A_log, Dp);
    // out_proj partials  [784x1024] K=2048 split-2
    hgemm<0, float><<<dim3(DM/128, (M2+127)/128, 2), 256>>>(
        p_yzh, p_woh, p_part, M2, DM, DI, DI, DI/2, nullptr);
    // residual + split-K reduce + final LN
    k_final<<<dim3(Tq, Bsz), 256>>>(ln_g, ln_b, out);
}